// round 9
// baseline (speedup 1.0000x reference)
#include <cuda_runtime.h>
#include <cuda_bf16.h>
#include <math.h>
#include <stdint.h>
#include <stddef.h>

// Problem constants
#define TT 256
#define BB 64
#define HH 1024
#define IN3H 3072          // 3*H
#define INK 2048           // input width of every layer (IN = 2H)
#define GX_M (TT * BB)     // 16384
#define GXSZ ((size_t)GX_M * IN3H)

#define REC_BLOCKS 144     // 2 dirs x 24 N-tiles(128) x 3 K-splits
#define REC_DBLOCKS 72     // blocks per direction
#define REC_THREADS 512    // 16 warps

// ---------------------------------------------------------------------------
// Scratch (device globals -- no allocation allowed)
// ---------------------------------------------------------------------------
__device__ float g_gx[2 * GXSZ];                        // input gates (fp32)
__device__ float g_ghp[3][2][2][(size_t)32 * IN3H];     // partials [ks][dir][grp]
__device__ float g_h [2 * BB * HH];                     // hidden state fp32
__device__ __nv_bfloat16 g_hhi[2 * BB * HH];            // hidden state hi/lo
__device__ __nv_bfloat16 g_hlo[2 * BB * HH];
__device__ __nv_bfloat16 g_ahi[(size_t)GX_M * INK];     // layer input hi/lo
__device__ __nv_bfloat16 g_alo[(size_t)GX_M * INK];
__device__ __nv_bfloat16 g_whi[(size_t)6 * IN3H * INK]; // w_ih hi/lo
__device__ __nv_bfloat16 g_wlo[(size_t)6 * IN3H * INK];
__device__ __nv_bfloat16 g_uhi[(size_t)6 * IN3H * HH];  // w_hh hi/lo
__device__ __nv_bfloat16 g_ulo[(size_t)6 * IN3H * HH];

// Monotonic arrive counters: [0..3]=P(dir,grp), [4..7]=H(dir,grp).
// Zeroed by a cudaMemsetAsync graph node before each recurrent launch.
__device__ unsigned g_ctr[8];

// ---------------------------------------------------------------------------
// Baseline-PTX helpers (valid on compute_103)
// ---------------------------------------------------------------------------
__device__ __forceinline__ uint32_t smem_u32(const void* p) {
    uint32_t a;
    asm("{ .reg .u64 t; cvta.to.shared.u64 t, %1; cvt.u32.u64 %0, t; }"
        : "=r"(a) : "l"(p));
    return a;
}

__device__ __forceinline__ void cp_async16(uint32_t dst, const void* src) {
    asm volatile("cp.async.cg.shared.global [%0], [%1], 16;"
                 :: "r"(dst), "l"(src) : "memory");
}
#define CP_COMMIT() asm volatile("cp.async.commit_group;" ::: "memory")
#define CP_WAIT0()  asm volatile("cp.async.wait_group 0;" ::: "memory")
#define CP_WAIT1()  asm volatile("cp.async.wait_group 1;" ::: "memory")

__device__ __forceinline__ void ldsm4(uint32_t* r, uint32_t addr) {
    asm volatile("ldmatrix.sync.aligned.m8n8.x4.shared.b16 {%0,%1,%2,%3}, [%4];"
                 : "=r"(r[0]), "=r"(r[1]), "=r"(r[2]), "=r"(r[3]) : "r"(addr));
}
__device__ __forceinline__ void ldsm2(uint32_t* r, uint32_t addr) {
    asm volatile("ldmatrix.sync.aligned.m8n8.x2.shared.b16 {%0,%1}, [%2];"
                 : "=r"(r[0]), "=r"(r[1]) : "r"(addr));
}

__device__ __forceinline__ void mma_bf16(float* c, const uint32_t* a,
                                         uint32_t b0, uint32_t b1) {
    asm("mma.sync.aligned.m16n8k16.row.col.f32.bf16.bf16.f32 "
        "{%0,%1,%2,%3}, {%4,%5,%6,%7}, {%8,%9}, {%0,%1,%2,%3};"
        : "+f"(c[0]), "+f"(c[1]), "+f"(c[2]), "+f"(c[3])
        : "r"(a[0]), "r"(a[1]), "r"(a[2]), "r"(a[3]), "r"(b0), "r"(b1));
}

__device__ __forceinline__ float fsigmoid(float x) {
    return 1.f / (1.f + __expf(-x));
}
__device__ __forceinline__ float ftanh(float x) {
    return 1.f - 2.f / (__expf(2.f * x) + 1.f);
}

// Split arrive/wait barrier on a monotonic counter
__device__ __forceinline__ void bar_arrive(unsigned* c) {
    __threadfence();
    __syncthreads();
    if (threadIdx.x == 0) atomicAdd(c, 1u);
}
__device__ __forceinline__ void bar_wait(unsigned* c, unsigned target) {
    if (threadIdx.x == 0) {
        while (*(volatile unsigned*)c < target) { }
    }
    __threadfence();
    __syncthreads();
}

// ---------------------------------------------------------------------------
// Split fp32 -> (bf16 hi, bf16 lo)
// ---------------------------------------------------------------------------
__device__ __forceinline__ uint32_t pack2bf(float a, float b) {
    __nv_bfloat162 t = __floats2bfloat162_rn(a, b);
    return *(uint32_t*)&t;
}

__global__ __launch_bounds__(256) void split_bf16_kernel(
    const float* __restrict__ src, __nv_bfloat16* __restrict__ hi,
    __nv_bfloat16* __restrict__ lo, size_t n4) {
    size_t i = (size_t)blockIdx.x * 256 + threadIdx.x;
    if (i >= n4) return;
    float4 v = ((const float4*)src)[i];
    float h0 = __bfloat162float(__float2bfloat16(v.x));
    float h1 = __bfloat162float(__float2bfloat16(v.y));
    float h2 = __bfloat162float(__float2bfloat16(v.z));
    float h3 = __bfloat162float(__float2bfloat16(v.w));
    uint2 hv, lv;
    hv.x = pack2bf(v.x, v.y);           hv.y = pack2bf(v.z, v.w);
    lv.x = pack2bf(v.x - h0, v.y - h1); lv.y = pack2bf(v.z - h2, v.w - h3);
    ((uint2*)hi)[i] = hv;
    ((uint2*)lo)[i] = lv;
}

// h0 -> g_h (fp32) + g_hhi/g_hlo (bf16 hi/lo). 2*B*H = 131072 elements.
__global__ __launch_bounds__(256) void split_h0_kernel(
    const float* __restrict__ h0_layer) {
    int i = blockIdx.x * 256 + threadIdx.x;
    float v = h0_layer[i];
    g_h[i] = v;
    __nv_bfloat16 hi = __float2bfloat16(v);
    g_hhi[i] = hi;
    g_hlo[i] = __float2bfloat16(v - __bfloat162float(hi));
}

// ---------------------------------------------------------------------------
// gx GEMM (unchanged from R6): 128x128 tile, k-chunk 32, 2-stage, 2 CTAs/SM.
// ---------------------------------------------------------------------------
#define GX_STAGE 40960
#define GX_SMEM  (2 * GX_STAGE)
#define GX_NCHUNK 64

__device__ __forceinline__ void gx_load(uint32_t sm, int bm, int bn, int k0,
                                        int tid, const __nv_bfloat16* Bhi,
                                        const __nv_bfloat16* Blo) {
#pragma unroll
    for (int half = 0; half < 2; half++) {
        int idx = half * 256 + tid;      // 0..511
        int r   = idx >> 2;
        int co  = k0 + (idx & 3) * 8;
        uint32_t dst = sm + r * 80 + (idx & 3) * 16;
        cp_async16(dst,          g_ahi + (size_t)(bm + r) * INK + co);
        cp_async16(dst + 10240,  g_alo + (size_t)(bm + r) * INK + co);
        cp_async16(dst + 20480,  Bhi   + (size_t)(bn + r) * INK + co);
        cp_async16(dst + 30720,  Blo   + (size_t)(bn + r) * INK + co);
    }
}

__global__ __launch_bounds__(256, 2) void gx_mma_kernel(
    const __nv_bfloat16* __restrict__ Whi,
    const __nv_bfloat16* __restrict__ Wlo,
    const float* __restrict__ bias)
{
    extern __shared__ char smem[];
    const uint32_t sb = smem_u32(smem);
    const int tid = threadIdx.x, wid = tid >> 5, lid = tid & 31;
    const int bn = blockIdx.x * 128;
    const int bm = blockIdx.y * 128;
    const int d  = blockIdx.z;

    const __nv_bfloat16* Bhi = Whi + (size_t)d * IN3H * INK;
    const __nv_bfloat16* Blo = Wlo + (size_t)d * IN3H * INK;
    const float* bptr = bias + d * IN3H;
    float* C = g_gx + (size_t)d * GXSZ;

    const uint32_t aoff = (uint32_t)(((wid & 3) * 32 + (lid & 7) + ((lid >> 3) & 1) * 8) * 80
                                     + ((lid >> 4) & 1) * 16);
    const uint32_t boff = (uint32_t)(((wid >> 2) * 64 + (lid & 7) + ((lid >> 4) & 1) * 8) * 80
                                     + ((lid >> 3) & 1) * 16);

    float acc[2][8][4];
#pragma unroll
    for (int i = 0; i < 2; i++)
#pragma unroll
        for (int j = 0; j < 8; j++)
#pragma unroll
            for (int q = 0; q < 4; q++) acc[i][j][q] = 0.f;

    gx_load(sb, bm, bn, 0, tid, Bhi, Blo); CP_COMMIT();

    for (int c = 0; c < GX_NCHUNK; c++) {
        if (c + 1 < GX_NCHUNK) {
            gx_load(sb + ((c + 1) & 1) * GX_STAGE, bm, bn, (c + 1) * 32, tid, Bhi, Blo);
            CP_COMMIT();
            CP_WAIT1();
        } else {
            CP_WAIT0();
        }
        __syncthreads();
        const uint32_t st = sb + (c & 1) * GX_STAGE;

#pragma unroll
        for (int kk = 0; kk < 2; kk++) {
            const uint32_t ko = kk * 32;
            uint32_t ah[2][4], al[2][4];
            ldsm4(ah[0], st + aoff + ko);
            ldsm4(ah[1], st + aoff + 1280 + ko);
            ldsm4(al[0], st + 10240 + aoff + ko);
            ldsm4(al[1], st + 10240 + aoff + 1280 + ko);
#pragma unroll
            for (int g = 0; g < 4; g++) {
                uint32_t bh[4], bl[4];
                ldsm4(bh, st + 20480 + boff + g * 1280 + ko);
                ldsm4(bl, st + 30720 + boff + g * 1280 + ko);
                mma_bf16(acc[0][2 * g],     ah[0], bh[0], bh[1]);
                mma_bf16(acc[0][2 * g + 1], ah[0], bh[2], bh[3]);
                mma_bf16(acc[1][2 * g],     ah[1], bh[0], bh[1]);
                mma_bf16(acc[1][2 * g + 1], ah[1], bh[2], bh[3]);
                mma_bf16(acc[0][2 * g],     ah[0], bl[0], bl[1]);
                mma_bf16(acc[0][2 * g + 1], ah[0], bl[2], bl[3]);
                mma_bf16(acc[1][2 * g],     ah[1], bl[0], bl[1]);
                mma_bf16(acc[1][2 * g + 1], ah[1], bl[2], bl[3]);
                mma_bf16(acc[0][2 * g],     al[0], bh[0], bh[1]);
                mma_bf16(acc[0][2 * g + 1], al[0], bh[2], bh[3]);
                mma_bf16(acc[1][2 * g],     al[1], bh[0], bh[1]);
                mma_bf16(acc[1][2 * g + 1], al[1], bh[2], bh[3]);
            }
        }
        __syncthreads();
    }

    const int lr = lid >> 2;
    const int lc = (lid & 3) * 2;
#pragma unroll
    for (int mt = 0; mt < 2; mt++) {
        const int row = bm + (wid & 3) * 32 + mt * 16 + lr;
#pragma unroll
        for (int nt = 0; nt < 8; nt++) {
            const int col = bn + (wid >> 2) * 64 + nt * 8 + lc;
            float b0 = bptr[col], b1 = bptr[col + 1];
            float* c = acc[mt][nt];
            C[(size_t)row * IN3H + col]           = c[0] + b0;
            C[(size_t)row * IN3H + col + 1]       = c[1] + b1;
            C[(size_t)(row + 8) * IN3H + col]     = c[2] + b0;
            C[(size_t)(row + 8) * IN3H + col + 1] = c[3] + b1;
        }
    }
}

// ---------------------------------------------------------------------------
// Persistent recurrent kernel, batch split into 2 groups of 32 for sync overlap.
// 144 blocks x 512 threads (16 warps). Weights resident in smem.
// smem map (dynamic, 190464 B):
//   A stages: [2][ hi 2560 | lo 2560 ]               @ 0      (10240)
//   B hi:     [chunk][128 rows][64 B, XOR-swizzled]  @ 10240  (90112)
//   B lo:                                            @ 100352 (90112)
// ---------------------------------------------------------------------------
#define RC_SB_BHI 10240
#define RC_SB_BLO 100352
#define RC_SMEM   190464

__global__ __launch_bounds__(REC_THREADS)
void gru_recurrent_kernel(const __nv_bfloat16* __restrict__ Uhi, // [2,3H,H]
                          const __nv_bfloat16* __restrict__ Ulo,
                          const float* __restrict__ bhh_layer,   // [2,3H]
                          float* __restrict__ hn_out)            // [2,B,H]
{
    extern __shared__ char smem[];
    const uint32_t sb = smem_u32(smem);
    const int bid = blockIdx.x, tid = threadIdx.x;
    const int wid = tid >> 5, lid = tid & 31;
    const int d    = bid / REC_DBLOCKS;
    const int lbid = bid % REC_DBLOCKS;
    const int nt  = lbid / 3;                  // 0..23 -> 128 gh columns
    const int ks  = lbid % 3;                  // K split
    const int bn0  = nt * 128;
    const int kbeg = ks * 352;                 // {0, 352, 704}
    const int nc   = (ks == 2) ? 10 : 11;      // chunks of 32 k

    const __nv_bfloat16* Whi = Uhi + (size_t)d * IN3H * HH;
    const __nv_bfloat16* Wlo = Ulo + (size_t)d * IN3H * HH;
    const float* biasd = bhh_layer + d * IN3H;

    unsigned* ctrP = &g_ctr[d * 2];        // [d*2 + g]
    unsigned* ctrH = &g_ctr[4 + d * 2];

    // ---- One-time weight preload into resident smem (swizzled 64B rows) ----
    for (int idx = tid; idx < nc * 512; idx += REC_THREADS) {
        int chunk = idx >> 9;
        int r     = (idx >> 2) & 127;
        int seg   = idx & 3;
        int col   = kbeg + chunk * 32 + seg * 8;
        uint32_t dst = (uint32_t)(chunk * 8192 + r * 64
                                  + ((seg ^ ((r >> 1) & 3)) * 16));
        cp_async16(sb + RC_SB_BHI + dst, Whi + (size_t)(bn0 + r) * HH + col);
        cp_async16(sb + RC_SB_BLO + dst, Wlo + (size_t)(bn0 + r) * HH + col);
    }
    CP_COMMIT();
    CP_WAIT0();
    __syncthreads();

    // A ldmatrix offset (80B padded rows, 32 rows): 16x16 tile
    const uint32_t aoff = (uint32_t)(((lid & 7) + ((lid >> 3) & 1) * 8) * 80
                                     + ((lid >> 4) & 1) * 16);
    // B ldmatrix x2 (64B rows, XOR swizzle): warp n-col = wid*8
    const int l15  = lid & 15;
    const int brow = wid * 8 + (l15 & 7);
    const int bkey = (brow >> 1) & 3;
    const int bhlf = (l15 >> 3) & 1;
    const uint32_t bseg0 = (uint32_t)(((0 + bhlf) ^ bkey) * 16);  // kk=0
    const uint32_t bseg1 = (uint32_t)(((2 + bhlf) ^ bkey) * 16);  // kk=1
    const uint32_t bbase = (uint32_t)(brow * 64);

    for (int s = 0; s < TT; s++) {
        // ================= GEMM phase, both groups =================
#pragma unroll 1
        for (int g = 0; g < 2; g++) {
            bar_wait(&ctrH[g], (unsigned)(REC_DBLOCKS * s));   // h(g, s-1) ready

            const __nv_bfloat16* hhi = g_hhi + (size_t)d * BB * HH + (size_t)g * 32 * HH;
            const __nv_bfloat16* hlo = g_hlo + (size_t)d * BB * HH + (size_t)g * 32 * HH;

            float acc[2][4];
#pragma unroll
            for (int i = 0; i < 2; i++)
#pragma unroll
                for (int q = 0; q < 4; q++) acc[i][q] = 0.f;

            // prologue A load, chunk 0: 32 rows x 32 k, hi+lo (256 threads)
            if (tid < 256) {
                int hl = tid >> 7;
                int r  = (tid >> 2) & 31;
                int sg = tid & 3;
                const __nv_bfloat16* src = (hl ? hlo : hhi)
                                           + (size_t)r * HH + kbeg + sg * 8;
                cp_async16(sb + hl * 2560 + r * 80 + sg * 16, src);
            }
            CP_COMMIT();

            for (int c = 0; c < nc; c++) {
                if (c + 1 < nc) {
                    if (tid < 256) {
                        int hl = tid >> 7;
                        int r  = (tid >> 2) & 31;
                        int sg = tid & 3;
                        const __nv_bfloat16* src = (hl ? hlo : hhi)
                            + (size_t)r * HH + kbeg + (c + 1) * 32 + sg * 8;
                        cp_async16(sb + ((c + 1) & 1) * 5120 + hl * 2560
                                   + r * 80 + sg * 16, src);
                    }
                    CP_COMMIT();
                    CP_WAIT1();
                } else {
                    CP_WAIT0();
                }
                __syncthreads();
                const uint32_t stA  = sb + (c & 1) * 5120;
                const uint32_t stBh = sb + RC_SB_BHI + c * 8192 + bbase;
                const uint32_t stBl = sb + RC_SB_BLO + c * 8192 + bbase;

#pragma unroll
                for (int kk = 0; kk < 2; kk++) {
                    const uint32_t ko  = kk * 32;
                    const uint32_t bso = kk ? bseg1 : bseg0;
                    uint32_t ah[2][4], al[2][4], bh[2], bl[2];
                    ldsm4(ah[0], stA + aoff + ko);
                    ldsm4(ah[1], stA + aoff + 1280 + ko);   // +16 rows * 80B
                    ldsm4(al[0], stA + 2560 + aoff + ko);
                    ldsm4(al[1], stA + 2560 + aoff + 1280 + ko);
                    ldsm2(bh, stBh + bso);
                    ldsm2(bl, stBl + bso);
                    mma_bf16(acc[0], ah[0], bh[0], bh[1]);
                    mma_bf16(acc[1], ah[1], bh[0], bh[1]);
                    mma_bf16(acc[0], ah[0], bl[0], bl[1]);
                    mma_bf16(acc[1], ah[1], bl[0], bl[1]);
                    mma_bf16(acc[0], al[0], bh[0], bh[1]);
                    mma_bf16(acc[1], al[1], bh[0], bh[1]);
                }
                __syncthreads();
            }

            // write 32x128 partial tile (warp cols wid*8)
            {
                float* Pout = g_ghp[ks][d][g];
                const int lr = lid >> 2;
                const int lc = (lid & 3) * 2;
                const int col = bn0 + wid * 8 + lc;
#pragma unroll
                for (int mt = 0; mt < 2; mt++) {
                    const int row = mt * 16 + lr;
                    float* c = acc[mt];
                    Pout[(size_t)row * IN3H + col]           = c[0];
                    Pout[(size_t)row * IN3H + col + 1]       = c[1];
                    Pout[(size_t)(row + 8) * IN3H + col]     = c[2];
                    Pout[(size_t)(row + 8) * IN3H + col + 1] = c[3];
                }
            }
            bar_arrive(&ctrP[g]);
        }

        // ================= Gate phase, both groups =================
        const int t = d ? (TT - 1 - s) : s;
#pragma unroll 1
        for (int g = 0; g < 2; g++) {
            bar_wait(&ctrP[g], (unsigned)(REC_DBLOCKS * (s + 1)));

            const int e = lbid * REC_THREADS + tid;    // covers 0..36863 >= 32768
            if (e < 32 * HH) {
                const int bl = e >> 10;                // batch row within group
                const int j  = e & 1023;
                const int b  = g * 32 + bl;
                const int i  = d * BB * HH + b * HH + j;

                const float* gxp = g_gx + (size_t)d * GXSZ
                                   + ((size_t)t * BB + b) * IN3H;
                const float* P0 = g_ghp[0][d][g] + (size_t)bl * IN3H;
                const float* P1 = g_ghp[1][d][g] + (size_t)bl * IN3H;
                const float* P2 = g_ghp[2][d][g] + (size_t)bl * IN3H;

                float ghr = P0[j]          + P1[j]          + P2[j]          + biasd[j];
                float ghz = P0[HH + j]     + P1[HH + j]     + P2[HH + j]     + biasd[HH + j];
                float ghn = P0[2 * HH + j] + P1[2 * HH + j] + P2[2 * HH + j] + biasd[2 * HH + j];

                float r = fsigmoid(gxp[j]      + ghr);
                float z = fsigmoid(gxp[HH + j] + ghz);
                float n = ftanh(gxp[2 * HH + j] + r * ghn);

                float hold = g_h[i];
                float hnew = n + z * (hold - n);
                g_h[i] = hnew;

                __nv_bfloat16 hi = __float2bfloat16(hnew);
                __nv_bfloat16 lo = __float2bfloat16(hnew - __bfloat162float(hi));
                g_hhi[i] = hi;
                g_hlo[i] = lo;

                size_t oidx = ((size_t)t * BB + b) * INK + (size_t)d * HH + j;
                g_ahi[oidx] = hi;
                g_alo[oidx] = lo;

                if (s == TT - 1) hn_out[i] = hnew;
            }
            bar_arrive(&ctrH[g]);
        }
    }
}

// ---------------------------------------------------------------------------
// Launch
// ---------------------------------------------------------------------------
extern "C" void kernel_launch(void* const* d_in, const int* in_sizes, int n_in,
                              void* d_out, int out_size) {
    const float* x   = (const float*)d_in[0];  // [T, B, 2048]
    const float* h0  = (const float*)d_in[1];  // [6, B, H]
    const float* wih = (const float*)d_in[2];  // [3, 2, 3072, 2048]
    const float* whh = (const float*)d_in[3];  // [3, 2, 3072, 1024]
    const float* bih = (const float*)d_in[4];  // [3, 2, 3072]
    const float* bhh = (const float*)d_in[5];  // [3, 2, 3072]
    float* out = (float*)d_out;                // [6, B, H]

    __nv_bfloat16 *ahi, *alo, *whi, *wlo, *uhi, *ulo;
    void* ctr;
    cudaGetSymbolAddress((void**)&ahi, g_ahi);
    cudaGetSymbolAddress((void**)&alo, g_alo);
    cudaGetSymbolAddress((void**)&whi, g_whi);
    cudaGetSymbolAddress((void**)&wlo, g_wlo);
    cudaGetSymbolAddress((void**)&uhi, g_uhi);
    cudaGetSymbolAddress((void**)&ulo, g_ulo);
    cudaGetSymbolAddress(&ctr, g_ctr);

    cudaFuncSetAttribute(gx_mma_kernel,
                         cudaFuncAttributeMaxDynamicSharedMemorySize, GX_SMEM);
    cudaFuncSetAttribute(gru_recurrent_kernel,
                         cudaFuncAttributeMaxDynamicSharedMemorySize, RC_SMEM);

    {   // split w_ih
        size_t n4 = (size_t)6 * IN3H * INK / 4;
        split_bf16_kernel<<<(unsigned)((n4 + 255) / 256), 256>>>(wih, whi, wlo, n4);
    }
    {   // split w_hh
        size_t n4 = (size_t)6 * IN3H * HH / 4;
        split_bf16_kernel<<<(unsigned)((n4 + 255) / 256), 256>>>(whh, uhi, ulo, n4);
    }
    {   // split x (layer-0 input)
        size_t n4 = (size_t)GX_M * INK / 4;
        split_bf16_kernel<<<(unsigned)((n4 + 255) / 256), 256>>>(x, ahi, alo, n4);
    }

    for (int l = 0; l < 3; l++) {
        gx_mma_kernel<<<dim3(IN3H / 128, GX_M / 128, 2), 256, GX_SMEM>>>(
            whi + (size_t)l * 2 * IN3H * INK,
            wlo + (size_t)l * 2 * IN3H * INK,
            bih + (size_t)l * 2 * IN3H);

        cudaMemsetAsync(ctr, 0, 8 * sizeof(unsigned));
        split_h0_kernel<<<(2 * BB * HH) / 256, 256>>>(h0 + (size_t)l * 2 * BB * HH);

        gru_recurrent_kernel<<<REC_BLOCKS, REC_THREADS, RC_SMEM>>>(
            uhi + (size_t)l * 2 * IN3H * HH,
            ulo + (size_t)l * 2 * IN3H * HH,
            bhh + (size_t)l * 2 * IN3H,
            out + (size_t)l * 2 * BB * HH);
    }
}

// round 10
// speedup vs baseline: 1.0372x; 1.0372x over previous
#include <cuda_runtime.h>
#include <cuda_bf16.h>
#include <math.h>
#include <stdint.h>
#include <stddef.h>

// Problem constants
#define TT 256
#define BB 64
#define HH 1024
#define IN3H 3072          // 3*H
#define INK 2048           // input width of every layer (IN = 2H)
#define GX_M (TT * BB)     // 16384
#define GXSZ ((size_t)GX_M * IN3H)

#define REC_BLOCKS 144     // 2 dirs * 24 N-tiles(128) * 3 K-splits
#define REC_THREADS 256

// ---------------------------------------------------------------------------
// Scratch (device globals -- no allocation allowed)
// ---------------------------------------------------------------------------
__device__ float g_gx[2 * GXSZ];                        // input gates (fp32)
__device__ float g_ghp[3][2][(size_t)BB * IN3H];        // hidden-gate partials
__device__ float g_h [2 * BB * HH];                     // hidden state fp32
__device__ __nv_bfloat16 g_hhi[2 * BB * HH];            // hidden state hi/lo
__device__ __nv_bfloat16 g_hlo[2 * BB * HH];
__device__ __nv_bfloat16 g_ahi[(size_t)GX_M * INK];     // layer input hi/lo
__device__ __nv_bfloat16 g_alo[(size_t)GX_M * INK];
__device__ __nv_bfloat16 g_whi[(size_t)6 * IN3H * INK]; // w_ih hi/lo
__device__ __nv_bfloat16 g_wlo[(size_t)6 * IN3H * INK];
__device__ __nv_bfloat16 g_uhi[(size_t)6 * IN3H * HH];  // w_hh hi/lo
__device__ __nv_bfloat16 g_ulo[(size_t)6 * IN3H * HH];

__device__ unsigned g_bar_count = 0;
__device__ unsigned g_bar_phase = 0;

// ---------------------------------------------------------------------------
// Baseline-PTX helpers (valid on compute_103)
// ---------------------------------------------------------------------------
__device__ __forceinline__ uint32_t smem_u32(const void* p) {
    uint32_t a;
    asm("{ .reg .u64 t; cvta.to.shared.u64 t, %1; cvt.u32.u64 %0, t; }"
        : "=r"(a) : "l"(p));
    return a;
}

__device__ __forceinline__ void cp_async16(uint32_t dst, const void* src) {
    asm volatile("cp.async.cg.shared.global [%0], [%1], 16;"
                 :: "r"(dst), "l"(src) : "memory");
}
#define CP_COMMIT() asm volatile("cp.async.commit_group;" ::: "memory")
#define CP_WAIT0()  asm volatile("cp.async.wait_group 0;" ::: "memory")
#define CP_WAIT1()  asm volatile("cp.async.wait_group 1;" ::: "memory")

__device__ __forceinline__ void ldsm4(uint32_t* r, uint32_t addr) {
    asm volatile("ldmatrix.sync.aligned.m8n8.x4.shared.b16 {%0,%1,%2,%3}, [%4];"
                 : "=r"(r[0]), "=r"(r[1]), "=r"(r[2]), "=r"(r[3]) : "r"(addr));
}

__device__ __forceinline__ void mma_bf16(float* c, const uint32_t* a,
                                         uint32_t b0, uint32_t b1) {
    asm("mma.sync.aligned.m16n8k16.row.col.f32.bf16.bf16.f32 "
        "{%0,%1,%2,%3}, {%4,%5,%6,%7}, {%8,%9}, {%0,%1,%2,%3};"
        : "+f"(c[0]), "+f"(c[1]), "+f"(c[2]), "+f"(c[3])
        : "r"(a[0]), "r"(a[1]), "r"(a[2]), "r"(a[3]), "r"(b0), "r"(b1));
}

// ---------------------------------------------------------------------------
// Split fp32 -> (bf16 hi, bf16 lo)
// ---------------------------------------------------------------------------
__device__ __forceinline__ uint32_t pack2bf(float a, float b) {
    __nv_bfloat162 t = __floats2bfloat162_rn(a, b);
    return *(uint32_t*)&t;
}

__global__ __launch_bounds__(256) void split_bf16_kernel(
    const float* __restrict__ src, __nv_bfloat16* __restrict__ hi,
    __nv_bfloat16* __restrict__ lo, size_t n4) {
    size_t i = (size_t)blockIdx.x * 256 + threadIdx.x;
    if (i >= n4) return;
    float4 v = ((const float4*)src)[i];
    float h0 = __bfloat162float(__float2bfloat16(v.x));
    float h1 = __bfloat162float(__float2bfloat16(v.y));
    float h2 = __bfloat162float(__float2bfloat16(v.z));
    float h3 = __bfloat162float(__float2bfloat16(v.w));
    uint2 hv, lv;
    hv.x = pack2bf(v.x, v.y);           hv.y = pack2bf(v.z, v.w);
    lv.x = pack2bf(v.x - h0, v.y - h1); lv.y = pack2bf(v.z - h2, v.w - h3);
    ((uint2*)hi)[i] = hv;
    ((uint2*)lo)[i] = lv;
}

// ---------------------------------------------------------------------------
// gx GEMM: 128x128 tile, k-chunk 32, 2-stage cp.async, 2 CTAs/SM.
// R10: all B fragments hoisted per k-slice -> accumulator reuse distance 16
// (was 4), eliminating HMMA RAW stalls.
// ---------------------------------------------------------------------------
#define GX_STAGE 40960
#define GX_SMEM  (2 * GX_STAGE)
#define GX_NCHUNK 64

__device__ __forceinline__ void gx_load(uint32_t sm, int bm, int bn, int k0,
                                        int tid, const __nv_bfloat16* Bhi,
                                        const __nv_bfloat16* Blo) {
#pragma unroll
    for (int half = 0; half < 2; half++) {
        int idx = half * 256 + tid;      // 0..511
        int r   = idx >> 2;
        int co  = k0 + (idx & 3) * 8;
        uint32_t dst = sm + r * 80 + (idx & 3) * 16;
        cp_async16(dst,          g_ahi + (size_t)(bm + r) * INK + co);
        cp_async16(dst + 10240,  g_alo + (size_t)(bm + r) * INK + co);
        cp_async16(dst + 20480,  Bhi   + (size_t)(bn + r) * INK + co);
        cp_async16(dst + 30720,  Blo   + (size_t)(bn + r) * INK + co);
    }
}

__global__ __launch_bounds__(256, 2) void gx_mma_kernel(
    const __nv_bfloat16* __restrict__ Whi,
    const __nv_bfloat16* __restrict__ Wlo,
    const float* __restrict__ bias)
{
    extern __shared__ char smem[];
    const uint32_t sb = smem_u32(smem);
    const int tid = threadIdx.x, wid = tid >> 5, lid = tid & 31;
    const int bn = blockIdx.x * 128;
    const int bm = blockIdx.y * 128;
    const int d  = blockIdx.z;

    const __nv_bfloat16* Bhi = Whi + (size_t)d * IN3H * INK;
    const __nv_bfloat16* Blo = Wlo + (size_t)d * IN3H * INK;
    const float* bptr = bias + d * IN3H;
    float* C = g_gx + (size_t)d * GXSZ;

    const uint32_t aoff = (uint32_t)(((wid & 3) * 32 + (lid & 7) + ((lid >> 3) & 1) * 8) * 80
                                     + ((lid >> 4) & 1) * 16);
    const uint32_t boff = (uint32_t)(((wid >> 2) * 64 + (lid & 7) + ((lid >> 4) & 1) * 8) * 80
                                     + ((lid >> 3) & 1) * 16);

    float acc[2][8][4];
#pragma unroll
    for (int i = 0; i < 2; i++)
#pragma unroll
        for (int j = 0; j < 8; j++)
#pragma unroll
            for (int q = 0; q < 4; q++) acc[i][j][q] = 0.f;

    gx_load(sb, bm, bn, 0, tid, Bhi, Blo); CP_COMMIT();

    for (int c = 0; c < GX_NCHUNK; c++) {
        if (c + 1 < GX_NCHUNK) {
            gx_load(sb + ((c + 1) & 1) * GX_STAGE, bm, bn, (c + 1) * 32, tid, Bhi, Blo);
            CP_COMMIT();
            CP_WAIT1();
        } else {
            CP_WAIT0();
        }
        __syncthreads();
        const uint32_t st = sb + (c & 1) * GX_STAGE;

#pragma unroll
        for (int kk = 0; kk < 2; kk++) {
            const uint32_t ko = kk * 32;
            uint32_t ah[2][4], al[2][4], bh[4][4], bl[4][4];
            ldsm4(ah[0], st + aoff + ko);
            ldsm4(ah[1], st + aoff + 1280 + ko);
            ldsm4(al[0], st + 10240 + aoff + ko);
            ldsm4(al[1], st + 10240 + aoff + 1280 + ko);
#pragma unroll
            for (int g = 0; g < 4; g++) {
                ldsm4(bh[g], st + 20480 + boff + g * 1280 + ko);
                ldsm4(bl[g], st + 30720 + boff + g * 1280 + ko);
            }
            // pass 1: hi*hi -- 16 mma, 16 distinct accumulators
#pragma unroll
            for (int g = 0; g < 4; g++) {
                mma_bf16(acc[0][2 * g],     ah[0], bh[g][0], bh[g][1]);
                mma_bf16(acc[0][2 * g + 1], ah[0], bh[g][2], bh[g][3]);
                mma_bf16(acc[1][2 * g],     ah[1], bh[g][0], bh[g][1]);
                mma_bf16(acc[1][2 * g + 1], ah[1], bh[g][2], bh[g][3]);
            }
            // pass 2: hi*lo
#pragma unroll
            for (int g = 0; g < 4; g++) {
                mma_bf16(acc[0][2 * g],     ah[0], bl[g][0], bl[g][1]);
                mma_bf16(acc[0][2 * g + 1], ah[0], bl[g][2], bl[g][3]);
                mma_bf16(acc[1][2 * g],     ah[1], bl[g][0], bl[g][1]);
                mma_bf16(acc[1][2 * g + 1], ah[1], bl[g][2], bl[g][3]);
            }
            // pass 3: lo*hi
#pragma unroll
            for (int g = 0; g < 4; g++) {
                mma_bf16(acc[0][2 * g],     al[0], bh[g][0], bh[g][1]);
                mma_bf16(acc[0][2 * g + 1], al[0], bh[g][2], bh[g][3]);
                mma_bf16(acc[1][2 * g],     al[1], bh[g][0], bh[g][1]);
                mma_bf16(acc[1][2 * g + 1], al[1], bh[g][2], bh[g][3]);
            }
        }
        __syncthreads();
    }

    const int lr = lid >> 2;
    const int lc = (lid & 3) * 2;
#pragma unroll
    for (int mt = 0; mt < 2; mt++) {
        const int row = bm + (wid & 3) * 32 + mt * 16 + lr;
#pragma unroll
        for (int nt = 0; nt < 8; nt++) {
            const int col = bn + (wid >> 2) * 64 + nt * 8 + lc;
            float b0 = bptr[col], b1 = bptr[col + 1];
            float* c = acc[mt][nt];
            C[(size_t)row * IN3H + col]           = c[0] + b0;
            C[(size_t)row * IN3H + col + 1]       = c[1] + b1;
            C[(size_t)(row + 8) * IN3H + col]     = c[2] + b0;
            C[(size_t)(row + 8) * IN3H + col + 1] = c[3] + b1;
        }
    }
}

// ---------------------------------------------------------------------------
// Grid-wide barrier (spin, monotonic phase) -- proven R6
// ---------------------------------------------------------------------------
__device__ __forceinline__ void grid_sync(unsigned& local_phase) {
    __threadfence();
    __syncthreads();
    if (threadIdx.x == 0) {
        unsigned ph = local_phase;
        if (atomicAdd(&g_bar_count, 1u) == REC_BLOCKS - 1) {
            g_bar_count = 0;
            __threadfence();
            atomicAdd(&g_bar_phase, 1u);
        } else {
            while (*(volatile unsigned*)&g_bar_phase == ph) { }
        }
        __threadfence();
    }
    __syncthreads();
    local_phase++;
}

// ---------------------------------------------------------------------------
// Persistent recurrent kernel -- VERBATIM R6 (best-known configuration).
// 144 blocks = 2 dirs x 24 N-tiles(128) x 3 K-splits ({352,352,320}).
// smem map (dynamic, 200704 B):
//   A stages: [2][ hi 5120 | lo 5120 ]                   @ 0      (20480)
//   B hi:     [chunk][128 rows][64 B, XOR-swizzled]      @ 20480  (90112)
//   B lo:                                                @ 110592 (90112)
// ---------------------------------------------------------------------------
#define RC_SB_BHI 20480
#define RC_SB_BLO 110592
#define RC_SMEM   200704

__global__ __launch_bounds__(REC_THREADS)
void gru_recurrent_kernel(const float* __restrict__ h0_layer,    // [2,B,H]
                          const __nv_bfloat16* __restrict__ Uhi, // [2,3H,H]
                          const __nv_bfloat16* __restrict__ Ulo,
                          const float* __restrict__ bhh_layer,   // [2,3H]
                          float* __restrict__ hn_out)            // [2,B,H]
{
    extern __shared__ char smem[];
    const uint32_t sb = smem_u32(smem);
    const int bid = blockIdx.x, tid = threadIdx.x;
    const int wid = tid >> 5, lid = tid & 31;
    const int d   = bid / 72;
    const int rem = bid % 72;
    const int nt  = rem / 3;            // 0..23 -> 128 gh columns each
    const int ks  = rem % 3;            // K split
    const int bn0  = nt * 128;
    const int kbeg = ks * 352;          // {0, 352, 704}
    const int nc   = (ks == 2) ? 10 : 11;   // chunks of 32 k

    const __nv_bfloat16* Whi = Uhi + (size_t)d * IN3H * HH;
    const __nv_bfloat16* Wlo = Ulo + (size_t)d * IN3H * HH;
    float* Pout = g_ghp[ks][d];

    unsigned phase = *(volatile unsigned*)&g_bar_phase;
    __syncthreads();

    // ---- One-time weight preload into resident smem (swizzled 64B rows) ----
    for (int idx = tid; idx < nc * 512; idx += REC_THREADS) {
        int chunk = idx >> 9;
        int r     = (idx >> 2) & 127;
        int seg   = idx & 3;
        int col   = kbeg + chunk * 32 + seg * 8;
        uint32_t dst = (uint32_t)(chunk * 8192 + r * 64
                                  + ((seg ^ ((r >> 1) & 3)) * 16));
        cp_async16(sb + RC_SB_BHI + dst, Whi + (size_t)(bn0 + r) * HH + col);
        cp_async16(sb + RC_SB_BLO + dst, Wlo + (size_t)(bn0 + r) * HH + col);
    }
    CP_COMMIT();
    CP_WAIT0();

    // Prologue: split h0 into fp32 + bf16 hi/lo state
    for (int i = bid * REC_THREADS + tid; i < 2 * BB * HH;
         i += REC_BLOCKS * REC_THREADS) {
        float v = h0_layer[i];
        g_h[i] = v;
        __nv_bfloat16 hi = __float2bfloat16(v);
        g_hhi[i] = hi;
        g_hlo[i] = __float2bfloat16(v - __bfloat162float(hi));
    }
    grid_sync(phase);

    // A ldmatrix offsets (80B padded rows): warp m = (wid&1)*32
    const uint32_t aoff = (uint32_t)(((wid & 1) * 32 + (lid & 7) + ((lid >> 3) & 1) * 8) * 80
                                     + ((lid >> 4) & 1) * 16);
    // B ldmatrix (64B rows, XOR swizzle): warp n = (wid>>1)*32
    const int brow0 = (wid >> 1) * 32 + (lid & 7) + ((lid >> 4) & 1) * 8;
    const int bkey  = (brow0 >> 1) & 3;
    const int lb3   = (lid >> 3) & 1;
    const uint32_t bseg0 = (uint32_t)(((0 + lb3) ^ bkey) * 16);  // kk=0
    const uint32_t bseg1 = (uint32_t)(((2 + lb3) ^ bkey) * 16);  // kk=1
    const uint32_t bbase = (uint32_t)(brow0 * 64);

    const __nv_bfloat16* hhi = g_hhi + (size_t)d * BB * HH;
    const __nv_bfloat16* hlo = g_hlo + (size_t)d * BB * HH;

    const int a_r  = tid >> 2;
    const int a_sg = tid & 3;

    for (int s = 0; s < TT; s++) {
        float acc[2][4][4];
#pragma unroll
        for (int i = 0; i < 2; i++)
#pragma unroll
            for (int j = 0; j < 4; j++)
#pragma unroll
                for (int q = 0; q < 4; q++) acc[i][j][q] = 0.f;

        {   // prologue A load, chunk 0
            uint32_t dst = sb + a_r * 80 + a_sg * 16;
            const int co = kbeg + a_sg * 8;
            cp_async16(dst,        hhi + (size_t)a_r * HH + co);
            cp_async16(dst + 5120, hlo + (size_t)a_r * HH + co);
            CP_COMMIT();
        }

        for (int c = 0; c < nc; c++) {
            if (c + 1 < nc) {
                uint32_t dst = sb + ((c + 1) & 1) * 10240 + a_r * 80 + a_sg * 16;
                const int co = kbeg + (c + 1) * 32 + a_sg * 8;
                cp_async16(dst,        hhi + (size_t)a_r * HH + co);
                cp_async16(dst + 5120, hlo + (size_t)a_r * HH + co);
                CP_COMMIT();
                CP_WAIT1();
            } else {
                CP_WAIT0();
            }
            __syncthreads();
            const uint32_t stA  = sb + (c & 1) * 10240;
            const uint32_t stBh = sb + RC_SB_BHI + c * 8192 + bbase;
            const uint32_t stBl = sb + RC_SB_BLO + c * 8192 + bbase;

#pragma unroll
            for (int kk = 0; kk < 2; kk++) {
                const uint32_t ko  = kk * 32;
                const uint32_t bso = kk ? bseg1 : bseg0;
                uint32_t ah[2][4], al[2][4], bh[2][4], bl[2][4];
                ldsm4(ah[0], stA + aoff + ko);
                ldsm4(ah[1], stA + aoff + 1280 + ko);
                ldsm4(al[0], stA + 5120 + aoff + ko);
                ldsm4(al[1], stA + 5120 + aoff + 1280 + ko);
                ldsm4(bh[0], stBh + bso);
                ldsm4(bh[1], stBh + 1024 + bso);   // +16 rows * 64B
                ldsm4(bl[0], stBl + bso);
                ldsm4(bl[1], stBl + 1024 + bso);
#pragma unroll
                for (int mt = 0; mt < 2; mt++)
#pragma unroll
                    for (int g = 0; g < 2; g++) {
                        mma_bf16(acc[mt][2 * g],     ah[mt], bh[g][0], bh[g][1]);
                        mma_bf16(acc[mt][2 * g + 1], ah[mt], bh[g][2], bh[g][3]);
                    }
#pragma unroll
                for (int mt = 0; mt < 2; mt++)
#pragma unroll
                    for (int g = 0; g < 2; g++) {
                        mma_bf16(acc[mt][2 * g],     ah[mt], bl[g][0], bl[g][1]);
                        mma_bf16(acc[mt][2 * g + 1], ah[mt], bl[g][2], bl[g][3]);
                    }
#pragma unroll
                for (int mt = 0; mt < 2; mt++)
#pragma unroll
                    for (int g = 0; g < 2; g++) {
                        mma_bf16(acc[mt][2 * g],     al[mt], bh[g][0], bh[g][1]);
                        mma_bf16(acc[mt][2 * g + 1], al[mt], bh[g][2], bh[g][3]);
                    }
            }
            __syncthreads();
        }

        // Epilogue: write 64x128 partial tile
        {
            const int lr = lid >> 2;
            const int lc = (lid & 3) * 2;
#pragma unroll
            for (int mt = 0; mt < 2; mt++) {
                const int row = (wid & 1) * 32 + mt * 16 + lr;
#pragma unroll
                for (int j = 0; j < 4; j++) {
                    const int col = bn0 + (wid >> 1) * 32 + j * 8 + lc;
                    float* c = acc[mt][j];
                    Pout[(size_t)row * IN3H + col]           = c[0];
                    Pout[(size_t)row * IN3H + col + 1]       = c[1];
                    Pout[(size_t)(row + 8) * IN3H + col]     = c[2];
                    Pout[(size_t)(row + 8) * IN3H + col + 1] = c[3];
                }
            }
        }

        grid_sync(phase);

        // Gate phase
        for (int i = bid * REC_THREADS + tid; i < 2 * BB * HH;
             i += REC_BLOCKS * REC_THREADS) {
            const int d2   = i >> 16;
            const int rem2 = i & 0xFFFF;
            const int b    = rem2 >> 10;
            const int j    = rem2 & 1023;
            const int t    = d2 ? (TT - 1 - s) : s;

            const float* gxp = g_gx + (size_t)d2 * GXSZ + ((size_t)t * BB + b) * IN3H;
            const float* P0 = g_ghp[0][d2] + (size_t)b * IN3H;
            const float* P1 = g_ghp[1][d2] + (size_t)b * IN3H;
            const float* P2 = g_ghp[2][d2] + (size_t)b * IN3H;
            const float* bias2 = bhh_layer + d2 * IN3H;

            float ghr = P0[j]          + P1[j]          + P2[j]          + bias2[j];
            float ghz = P0[HH + j]     + P1[HH + j]     + P2[HH + j]     + bias2[HH + j];
            float ghn = P0[2 * HH + j] + P1[2 * HH + j] + P2[2 * HH + j] + bias2[2 * HH + j];

            float r = 1.f / (1.f + expf(-(gxp[j]      + ghr)));
            float z = 1.f / (1.f + expf(-(gxp[HH + j] + ghz)));
            float n = tanhf(gxp[2 * HH + j] + r * ghn);

            float hold = g_h[i];
            float hnew = n + z * (hold - n);
            g_h[i] = hnew;

            __nv_bfloat16 hi = __float2bfloat16(hnew);
            __nv_bfloat16 lo = __float2bfloat16(hnew - __bfloat162float(hi));
            g_hhi[i] = hi;
            g_hlo[i] = lo;

            size_t oidx = ((size_t)t * BB + b) * INK + (size_t)d2 * HH + j;
            g_ahi[oidx] = hi;
            g_alo[oidx] = lo;

            if (s == TT - 1) hn_out[i] = hnew;
        }

        grid_sync(phase);
    }
}

// ---------------------------------------------------------------------------
// Launch
// ---------------------------------------------------------------------------
extern "C" void kernel_launch(void* const* d_in, const int* in_sizes, int n_in,
                              void* d_out, int out_size) {
    const float* x   = (const float*)d_in[0];  // [T, B, 2048]
    const float* h0  = (const float*)d_in[1];  // [6, B, H]
    const float* wih = (const float*)d_in[2];  // [3, 2, 3072, 2048]
    const float* whh = (const float*)d_in[3];  // [3, 2, 3072, 1024]
    const float* bih = (const float*)d_in[4];  // [3, 2, 3072]
    const float* bhh = (const float*)d_in[5];  // [3, 2, 3072]
    float* out = (float*)d_out;                // [6, B, H]

    __nv_bfloat16 *ahi, *alo, *whi, *wlo, *uhi, *ulo;
    cudaGetSymbolAddress((void**)&ahi, g_ahi);
    cudaGetSymbolAddress((void**)&alo, g_alo);
    cudaGetSymbolAddress((void**)&whi, g_whi);
    cudaGetSymbolAddress((void**)&wlo, g_wlo);
    cudaGetSymbolAddress((void**)&uhi, g_uhi);
    cudaGetSymbolAddress((void**)&ulo, g_ulo);

    cudaFuncSetAttribute(gx_mma_kernel,
                         cudaFuncAttributeMaxDynamicSharedMemorySize, GX_SMEM);
    cudaFuncSetAttribute(gru_recurrent_kernel,
                         cudaFuncAttributeMaxDynamicSharedMemorySize, RC_SMEM);

    {   // split w_ih
        size_t n4 = (size_t)6 * IN3H * INK / 4;
        split_bf16_kernel<<<(unsigned)((n4 + 255) / 256), 256>>>(wih, whi, wlo, n4);
    }
    {   // split w_hh
        size_t n4 = (size_t)6 * IN3H * HH / 4;
        split_bf16_kernel<<<(unsigned)((n4 + 255) / 256), 256>>>(whh, uhi, ulo, n4);
    }
    {   // split x (layer-0 input)
        size_t n4 = (size_t)GX_M * INK / 4;
        split_bf16_kernel<<<(unsigned)((n4 + 255) / 256), 256>>>(x, ahi, alo, n4);
    }

    for (int l = 0; l < 3; l++) {
        gx_mma_kernel<<<dim3(IN3H / 128, GX_M / 128, 2), 256, GX_SMEM>>>(
            whi + (size_t)l * 2 * IN3H * INK,
            wlo + (size_t)l * 2 * IN3H * INK,
            bih + (size_t)l * 2 * IN3H);

        gru_recurrent_kernel<<<REC_BLOCKS, REC_THREADS, RC_SMEM>>>(
            h0  + (size_t)l * 2 * BB * HH,
            uhi + (size_t)l * 2 * IN3H * HH,
            ulo + (size_t)l * 2 * IN3H * HH,
            bhh + (size_t)l * 2 * IN3H,
            out + (size_t)l * 2 * BB * HH);
    }
}

// round 11
// speedup vs baseline: 1.2202x; 1.1764x over previous
#include <cuda_runtime.h>
#include <cuda_bf16.h>
#include <math.h>
#include <stdint.h>
#include <stddef.h>

// Problem constants
#define TT 256
#define BB 64
#define HH 1024
#define IN3H 3072          // 3*H
#define INK 2048           // input width of every layer (IN = 2H)
#define GX_M (TT * BB)     // 16384
#define GXSZ ((size_t)GX_M * IN3H)

#define REC_BLOCKS 144     // 2 dirs * 24 N-tiles(128) * 3 K-splits
#define REC_THREADS 256

// ---------------------------------------------------------------------------
// Scratch (device globals -- no allocation allowed)
// ---------------------------------------------------------------------------
__device__ float g_gx[2 * GXSZ];                        // input gates (fp32)
__device__ float g_ghp[3][2][(size_t)BB * IN3H];        // hidden-gate partials
__device__ float g_h [2 * BB * HH];                     // hidden state fp32
__device__ __nv_bfloat16 g_hhi[2 * BB * HH];            // hidden state hi/lo
__device__ __nv_bfloat16 g_hlo[2 * BB * HH];
__device__ __nv_bfloat16 g_ahi[(size_t)GX_M * INK];     // layer input hi/lo
__device__ __nv_bfloat16 g_alo[(size_t)GX_M * INK];
__device__ __nv_bfloat16 g_whi[(size_t)6 * IN3H * INK]; // w_ih hi/lo
__device__ __nv_bfloat16 g_wlo[(size_t)6 * IN3H * INK];
__device__ __nv_bfloat16 g_uhi[(size_t)6 * IN3H * HH];  // w_hh hi/lo
__device__ __nv_bfloat16 g_ulo[(size_t)6 * IN3H * HH];

__device__ unsigned g_bar_count = 0;
__device__ unsigned g_bar_phase = 0;

// ---------------------------------------------------------------------------
// Baseline-PTX helpers (valid on compute_103)
// ---------------------------------------------------------------------------
__device__ __forceinline__ uint32_t smem_u32(const void* p) {
    uint32_t a;
    asm("{ .reg .u64 t; cvta.to.shared.u64 t, %1; cvt.u32.u64 %0, t; }"
        : "=r"(a) : "l"(p));
    return a;
}

__device__ __forceinline__ void cp_async16(uint32_t dst, const void* src) {
    asm volatile("cp.async.cg.shared.global [%0], [%1], 16;"
                 :: "r"(dst), "l"(src) : "memory");
}
#define CP_COMMIT() asm volatile("cp.async.commit_group;" ::: "memory")
#define CP_WAIT0()  asm volatile("cp.async.wait_group 0;" ::: "memory")
#define CP_WAIT1()  asm volatile("cp.async.wait_group 1;" ::: "memory")

__device__ __forceinline__ void ldsm4(uint32_t* r, uint32_t addr) {
    asm volatile("ldmatrix.sync.aligned.m8n8.x4.shared.b16 {%0,%1,%2,%3}, [%4];"
                 : "=r"(r[0]), "=r"(r[1]), "=r"(r[2]), "=r"(r[3]) : "r"(addr));
}

__device__ __forceinline__ void mma_bf16(float* c, const uint32_t* a,
                                         uint32_t b0, uint32_t b1) {
    asm("mma.sync.aligned.m16n8k16.row.col.f32.bf16.bf16.f32 "
        "{%0,%1,%2,%3}, {%4,%5,%6,%7}, {%8,%9}, {%0,%1,%2,%3};"
        : "+f"(c[0]), "+f"(c[1]), "+f"(c[2]), "+f"(c[3])
        : "r"(a[0]), "r"(a[1]), "r"(a[2]), "r"(a[3]), "r"(b0), "r"(b1));
}

__device__ __forceinline__ void prefetch_l2(const void* p) {
    asm volatile("prefetch.global.L2 [%0];" :: "l"(p));
}

// ---------------------------------------------------------------------------
// Split fp32 -> (bf16 hi, bf16 lo)
// ---------------------------------------------------------------------------
__device__ __forceinline__ uint32_t pack2bf(float a, float b) {
    __nv_bfloat162 t = __floats2bfloat162_rn(a, b);
    return *(uint32_t*)&t;
}

__global__ __launch_bounds__(256) void split_bf16_kernel(
    const float* __restrict__ src, __nv_bfloat16* __restrict__ hi,
    __nv_bfloat16* __restrict__ lo, size_t n4) {
    size_t i = (size_t)blockIdx.x * 256 + threadIdx.x;
    if (i >= n4) return;
    float4 v = ((const float4*)src)[i];
    float h0 = __bfloat162float(__float2bfloat16(v.x));
    float h1 = __bfloat162float(__float2bfloat16(v.y));
    float h2 = __bfloat162float(__float2bfloat16(v.z));
    float h3 = __bfloat162float(__float2bfloat16(v.w));
    uint2 hv, lv;
    hv.x = pack2bf(v.x, v.y);           hv.y = pack2bf(v.z, v.w);
    lv.x = pack2bf(v.x - h0, v.y - h1); lv.y = pack2bf(v.z - h2, v.w - h3);
    ((uint2*)hi)[i] = hv;
    ((uint2*)lo)[i] = lv;
}

// ---------------------------------------------------------------------------
// gx GEMM -- VERBATIM R6 (63.3% tensor, best measured): 128x128 tile,
// k-chunk 32, 2-stage cp.async, 2 CTAs/SM.
// ---------------------------------------------------------------------------
#define GX_STAGE 40960
#define GX_SMEM  (2 * GX_STAGE)
#define GX_NCHUNK 64

__device__ __forceinline__ void gx_load(uint32_t sm, int bm, int bn, int k0,
                                        int tid, const __nv_bfloat16* Bhi,
                                        const __nv_bfloat16* Blo) {
#pragma unroll
    for (int half = 0; half < 2; half++) {
        int idx = half * 256 + tid;      // 0..511
        int r   = idx >> 2;
        int co  = k0 + (idx & 3) * 8;
        uint32_t dst = sm + r * 80 + (idx & 3) * 16;
        cp_async16(dst,          g_ahi + (size_t)(bm + r) * INK + co);
        cp_async16(dst + 10240,  g_alo + (size_t)(bm + r) * INK + co);
        cp_async16(dst + 20480,  Bhi   + (size_t)(bn + r) * INK + co);
        cp_async16(dst + 30720,  Blo   + (size_t)(bn + r) * INK + co);
    }
}

__global__ __launch_bounds__(256, 2) void gx_mma_kernel(
    const __nv_bfloat16* __restrict__ Whi,
    const __nv_bfloat16* __restrict__ Wlo,
    const float* __restrict__ bias)
{
    extern __shared__ char smem[];
    const uint32_t sb = smem_u32(smem);
    const int tid = threadIdx.x, wid = tid >> 5, lid = tid & 31;
    const int bn = blockIdx.x * 128;
    const int bm = blockIdx.y * 128;
    const int d  = blockIdx.z;

    const __nv_bfloat16* Bhi = Whi + (size_t)d * IN3H * INK;
    const __nv_bfloat16* Blo = Wlo + (size_t)d * IN3H * INK;
    const float* bptr = bias + d * IN3H;
    float* C = g_gx + (size_t)d * GXSZ;

    const uint32_t aoff = (uint32_t)(((wid & 3) * 32 + (lid & 7) + ((lid >> 3) & 1) * 8) * 80
                                     + ((lid >> 4) & 1) * 16);
    const uint32_t boff = (uint32_t)(((wid >> 2) * 64 + (lid & 7) + ((lid >> 4) & 1) * 8) * 80
                                     + ((lid >> 3) & 1) * 16);

    float acc[2][8][4];
#pragma unroll
    for (int i = 0; i < 2; i++)
#pragma unroll
        for (int j = 0; j < 8; j++)
#pragma unroll
            for (int q = 0; q < 4; q++) acc[i][j][q] = 0.f;

    gx_load(sb, bm, bn, 0, tid, Bhi, Blo); CP_COMMIT();

    for (int c = 0; c < GX_NCHUNK; c++) {
        if (c + 1 < GX_NCHUNK) {
            gx_load(sb + ((c + 1) & 1) * GX_STAGE, bm, bn, (c + 1) * 32, tid, Bhi, Blo);
            CP_COMMIT();
            CP_WAIT1();
        } else {
            CP_WAIT0();
        }
        __syncthreads();
        const uint32_t st = sb + (c & 1) * GX_STAGE;

#pragma unroll
        for (int kk = 0; kk < 2; kk++) {
            const uint32_t ko = kk * 32;
            uint32_t ah[2][4], al[2][4];
            ldsm4(ah[0], st + aoff + ko);
            ldsm4(ah[1], st + aoff + 1280 + ko);
            ldsm4(al[0], st + 10240 + aoff + ko);
            ldsm4(al[1], st + 10240 + aoff + 1280 + ko);
#pragma unroll
            for (int g = 0; g < 4; g++) {
                uint32_t bh[4], bl[4];
                ldsm4(bh, st + 20480 + boff + g * 1280 + ko);
                ldsm4(bl, st + 30720 + boff + g * 1280 + ko);
                mma_bf16(acc[0][2 * g],     ah[0], bh[0], bh[1]);
                mma_bf16(acc[0][2 * g + 1], ah[0], bh[2], bh[3]);
                mma_bf16(acc[1][2 * g],     ah[1], bh[0], bh[1]);
                mma_bf16(acc[1][2 * g + 1], ah[1], bh[2], bh[3]);
                mma_bf16(acc[0][2 * g],     ah[0], bl[0], bl[1]);
                mma_bf16(acc[0][2 * g + 1], ah[0], bl[2], bl[3]);
                mma_bf16(acc[1][2 * g],     ah[1], bl[0], bl[1]);
                mma_bf16(acc[1][2 * g + 1], ah[1], bl[2], bl[3]);
                mma_bf16(acc[0][2 * g],     al[0], bh[0], bh[1]);
                mma_bf16(acc[0][2 * g + 1], al[0], bh[2], bh[3]);
                mma_bf16(acc[1][2 * g],     al[1], bh[0], bh[1]);
                mma_bf16(acc[1][2 * g + 1], al[1], bh[2], bh[3]);
            }
        }
        __syncthreads();
    }

    const int lr = lid >> 2;
    const int lc = (lid & 3) * 2;
#pragma unroll
    for (int mt = 0; mt < 2; mt++) {
        const int row = bm + (wid & 3) * 32 + mt * 16 + lr;
#pragma unroll
        for (int nt = 0; nt < 8; nt++) {
            const int col = bn + (wid >> 2) * 64 + nt * 8 + lc;
            float b0 = bptr[col], b1 = bptr[col + 1];
            float* c = acc[mt][nt];
            C[(size_t)row * IN3H + col]           = c[0] + b0;
            C[(size_t)row * IN3H + col + 1]       = c[1] + b1;
            C[(size_t)(row + 8) * IN3H + col]     = c[2] + b0;
            C[(size_t)(row + 8) * IN3H + col + 1] = c[3] + b1;
        }
    }
}

// ---------------------------------------------------------------------------
// Grid-wide barrier (spin, monotonic phase) -- proven R6
// ---------------------------------------------------------------------------
__device__ __forceinline__ void grid_sync(unsigned& local_phase) {
    __threadfence();
    __syncthreads();
    if (threadIdx.x == 0) {
        unsigned ph = local_phase;
        if (atomicAdd(&g_bar_count, 1u) == REC_BLOCKS - 1) {
            g_bar_count = 0;
            __threadfence();
            atomicAdd(&g_bar_phase, 1u);
        } else {
            while (*(volatile unsigned*)&g_bar_phase == ph) { }
        }
        __threadfence();
    }
    __syncthreads();
    local_phase++;
}

// ---------------------------------------------------------------------------
// Persistent recurrent kernel -- R6 structure; R11 adds (a) L2 prefetch of
// this step's gx rows at GEMM start, (b) float2-vectorized gate phase.
// 144 blocks = 2 dirs x 24 N-tiles(128) x 3 K-splits ({352,352,320}).
// smem map (dynamic, 200704 B):
//   A stages: [2][ hi 5120 | lo 5120 ]                   @ 0      (20480)
//   B hi:     [chunk][128 rows][64 B, XOR-swizzled]      @ 20480  (90112)
//   B lo:                                                @ 110592 (90112)
// ---------------------------------------------------------------------------
#define RC_SB_BHI 20480
#define RC_SB_BLO 110592
#define RC_SMEM   200704

__global__ __launch_bounds__(REC_THREADS)
void gru_recurrent_kernel(const float* __restrict__ h0_layer,    // [2,B,H]
                          const __nv_bfloat16* __restrict__ Uhi, // [2,3H,H]
                          const __nv_bfloat16* __restrict__ Ulo,
                          const float* __restrict__ bhh_layer,   // [2,3H]
                          float* __restrict__ hn_out)            // [2,B,H]
{
    extern __shared__ char smem[];
    const uint32_t sb = smem_u32(smem);
    const int bid = blockIdx.x, tid = threadIdx.x;
    const int wid = tid >> 5, lid = tid & 31;
    const int d   = bid / 72;
    const int rem = bid % 72;
    const int nt  = rem / 3;            // 0..23 -> 128 gh columns each
    const int ks  = rem % 3;            // K split
    const int bn0  = nt * 128;
    const int kbeg = ks * 352;          // {0, 352, 704}
    const int nc   = (ks == 2) ? 10 : 11;   // chunks of 32 k

    const __nv_bfloat16* Whi = Uhi + (size_t)d * IN3H * HH;
    const __nv_bfloat16* Wlo = Ulo + (size_t)d * IN3H * HH;
    float* Pout = g_ghp[ks][d];

    unsigned phase = *(volatile unsigned*)&g_bar_phase;
    __syncthreads();

    // ---- One-time weight preload into resident smem (swizzled 64B rows) ----
    for (int idx = tid; idx < nc * 512; idx += REC_THREADS) {
        int chunk = idx >> 9;
        int r     = (idx >> 2) & 127;
        int seg   = idx & 3;
        int col   = kbeg + chunk * 32 + seg * 8;
        uint32_t dst = (uint32_t)(chunk * 8192 + r * 64
                                  + ((seg ^ ((r >> 1) & 3)) * 16));
        cp_async16(sb + RC_SB_BHI + dst, Whi + (size_t)(bn0 + r) * HH + col);
        cp_async16(sb + RC_SB_BLO + dst, Wlo + (size_t)(bn0 + r) * HH + col);
    }
    CP_COMMIT();
    CP_WAIT0();

    // Prologue: split h0 into fp32 + bf16 hi/lo state
    for (int i = bid * REC_THREADS + tid; i < 2 * BB * HH;
         i += REC_BLOCKS * REC_THREADS) {
        float v = h0_layer[i];
        g_h[i] = v;
        __nv_bfloat16 hi = __float2bfloat16(v);
        g_hhi[i] = hi;
        g_hlo[i] = __float2bfloat16(v - __bfloat162float(hi));
    }
    grid_sync(phase);

    // A ldmatrix offsets (80B padded rows): warp m = (wid&1)*32
    const uint32_t aoff = (uint32_t)(((wid & 1) * 32 + (lid & 7) + ((lid >> 3) & 1) * 8) * 80
                                     + ((lid >> 4) & 1) * 16);
    // B ldmatrix (64B rows, XOR swizzle): warp n = (wid>>1)*32
    const int brow0 = (wid >> 1) * 32 + (lid & 7) + ((lid >> 4) & 1) * 8;
    const int bkey  = (brow0 >> 1) & 3;
    const int lb3   = (lid >> 3) & 1;
    const uint32_t bseg0 = (uint32_t)(((0 + lb3) ^ bkey) * 16);  // kk=0
    const uint32_t bseg1 = (uint32_t)(((2 + lb3) ^ bkey) * 16);  // kk=1
    const uint32_t bbase = (uint32_t)(brow0 * 64);

    const __nv_bfloat16* hhi = g_hhi + (size_t)d * BB * HH;
    const __nv_bfloat16* hlo = g_hlo + (size_t)d * BB * HH;

    const int a_r  = tid >> 2;
    const int a_sg = tid & 3;

    for (int s = 0; s < TT; s++) {
        float acc[2][4][4];
#pragma unroll
        for (int i = 0; i < 2; i++)
#pragma unroll
            for (int j = 0; j < 4; j++)
#pragma unroll
                for (int q = 0; q < 4; q++) acc[i][j][q] = 0.f;

        {   // prologue A load, chunk 0
            uint32_t dst = sb + a_r * 80 + a_sg * 16;
            const int co = kbeg + a_sg * 8;
            cp_async16(dst,        hhi + (size_t)a_r * HH + co);
            cp_async16(dst + 5120, hlo + (size_t)a_r * HH + co);
            CP_COMMIT();
        }

        // R11: prefetch this step's gx rows into L2 (gate reads them after
        // the GEMM phase; the ~10us of GEMM hides the DRAM fetch).
        {
            const int ln = bid * REC_THREADS + tid;   // 36864 threads
            if (ln < 6144) {   // dir 0: 64 rows * 3072 f32 = 6144 lines
                prefetch_l2(g_gx + (size_t)s * BB * IN3H + (size_t)ln * 32);
            } else if (ln < 12288) {  // dir 1, time TT-1-s
                prefetch_l2(g_gx + GXSZ + (size_t)(TT - 1 - s) * BB * IN3H
                            + (size_t)(ln - 6144) * 32);
            }
        }

        for (int c = 0; c < nc; c++) {
            if (c + 1 < nc) {
                uint32_t dst = sb + ((c + 1) & 1) * 10240 + a_r * 80 + a_sg * 16;
                const int co = kbeg + (c + 1) * 32 + a_sg * 8;
                cp_async16(dst,        hhi + (size_t)a_r * HH + co);
                cp_async16(dst + 5120, hlo + (size_t)a_r * HH + co);
                CP_COMMIT();
                CP_WAIT1();
            } else {
                CP_WAIT0();
            }
            __syncthreads();
            const uint32_t stA  = sb + (c & 1) * 10240;
            const uint32_t stBh = sb + RC_SB_BHI + c * 8192 + bbase;
            const uint32_t stBl = sb + RC_SB_BLO + c * 8192 + bbase;

#pragma unroll
            for (int kk = 0; kk < 2; kk++) {
                const uint32_t ko  = kk * 32;
                const uint32_t bso = kk ? bseg1 : bseg0;
                uint32_t ah[2][4], al[2][4], bh[2][4], bl[2][4];
                ldsm4(ah[0], stA + aoff + ko);
                ldsm4(ah[1], stA + aoff + 1280 + ko);
                ldsm4(al[0], stA + 5120 + aoff + ko);
                ldsm4(al[1], stA + 5120 + aoff + 1280 + ko);
                ldsm4(bh[0], stBh + bso);
                ldsm4(bh[1], stBh + 1024 + bso);   // +16 rows * 64B
                ldsm4(bl[0], stBl + bso);
                ldsm4(bl[1], stBl + 1024 + bso);
#pragma unroll
                for (int mt = 0; mt < 2; mt++)
#pragma unroll
                    for (int g = 0; g < 2; g++) {
                        mma_bf16(acc[mt][2 * g],     ah[mt], bh[g][0], bh[g][1]);
                        mma_bf16(acc[mt][2 * g + 1], ah[mt], bh[g][2], bh[g][3]);
                    }
#pragma unroll
                for (int mt = 0; mt < 2; mt++)
#pragma unroll
                    for (int g = 0; g < 2; g++) {
                        mma_bf16(acc[mt][2 * g],     ah[mt], bl[g][0], bl[g][1]);
                        mma_bf16(acc[mt][2 * g + 1], ah[mt], bl[g][2], bl[g][3]);
                    }
#pragma unroll
                for (int mt = 0; mt < 2; mt++)
#pragma unroll
                    for (int g = 0; g < 2; g++) {
                        mma_bf16(acc[mt][2 * g],     al[mt], bh[g][0], bh[g][1]);
                        mma_bf16(acc[mt][2 * g + 1], al[mt], bh[g][2], bh[g][3]);
                    }
            }
            __syncthreads();
        }

        // Epilogue: write 64x128 partial tile
        {
            const int lr = lid >> 2;
            const int lc = (lid & 3) * 2;
#pragma unroll
            for (int mt = 0; mt < 2; mt++) {
                const int row = (wid & 1) * 32 + mt * 16 + lr;
#pragma unroll
                for (int j = 0; j < 4; j++) {
                    const int col = bn0 + (wid >> 1) * 32 + j * 8 + lc;
                    float* c = acc[mt][j];
                    Pout[(size_t)row * IN3H + col]           = c[0];
                    Pout[(size_t)row * IN3H + col + 1]       = c[1];
                    Pout[(size_t)(row + 8) * IN3H + col]     = c[2];
                    Pout[(size_t)(row + 8) * IN3H + col + 1] = c[3];
                }
            }
        }

        grid_sync(phase);

        // Gate phase -- float2 vectorized (65536 pairs over the grid)
        for (int p = bid * REC_THREADS + tid; p < 65536;
             p += REC_BLOCKS * REC_THREADS) {
            const int d2  = p >> 15;              // 32768 pairs per dir
            const int rm  = p & 32767;
            const int b   = rm >> 9;              // 512 pairs per batch row
            const int jp  = (rm & 511) << 1;      // even j
            const int i   = d2 * BB * HH + b * HH + jp;
            const int t   = d2 ? (TT - 1 - s) : s;

            const float* gxp = g_gx + (size_t)d2 * GXSZ + ((size_t)t * BB + b) * IN3H;
            const float* P0 = g_ghp[0][d2] + (size_t)b * IN3H;
            const float* P1 = g_ghp[1][d2] + (size_t)b * IN3H;
            const float* P2 = g_ghp[2][d2] + (size_t)b * IN3H;
            const float* bias2 = bhh_layer + d2 * IN3H;

            float2 gr  = *(const float2*)(gxp + jp);
            float2 gz  = *(const float2*)(gxp + HH + jp);
            float2 gn  = *(const float2*)(gxp + 2 * HH + jp);
            float2 p0r = *(const float2*)(P0 + jp);
            float2 p0z = *(const float2*)(P0 + HH + jp);
            float2 p0n = *(const float2*)(P0 + 2 * HH + jp);
            float2 p1r = *(const float2*)(P1 + jp);
            float2 p1z = *(const float2*)(P1 + HH + jp);
            float2 p1n = *(const float2*)(P1 + 2 * HH + jp);
            float2 p2r = *(const float2*)(P2 + jp);
            float2 p2z = *(const float2*)(P2 + HH + jp);
            float2 p2n = *(const float2*)(P2 + 2 * HH + jp);
            float2 br  = *(const float2*)(bias2 + jp);
            float2 bz  = *(const float2*)(bias2 + HH + jp);
            float2 bn2 = *(const float2*)(bias2 + 2 * HH + jp);
            float2 ho  = *(const float2*)(g_h + i);

            float hnew[2];
#pragma unroll
            for (int q = 0; q < 2; q++) {
                float ghr = (q ? p0r.y + p1r.y + p2r.y + br.y
                               : p0r.x + p1r.x + p2r.x + br.x);
                float ghz = (q ? p0z.y + p1z.y + p2z.y + bz.y
                               : p0z.x + p1z.x + p2z.x + bz.x);
                float ghn = (q ? p0n.y + p1n.y + p2n.y + bn2.y
                               : p0n.x + p1n.x + p2n.x + bn2.x);
                float gxr = q ? gr.y : gr.x;
                float gxz = q ? gz.y : gz.x;
                float gxn = q ? gn.y : gn.x;
                float hol = q ? ho.y : ho.x;

                float r = 1.f / (1.f + expf(-(gxr + ghr)));
                float z = 1.f / (1.f + expf(-(gxz + ghz)));
                float n = tanhf(gxn + r * ghn);
                hnew[q] = n + z * (hol - n);
            }

            *(float2*)(g_h + i) = make_float2(hnew[0], hnew[1]);

            __nv_bfloat162 h2 = __floats2bfloat162_rn(hnew[0], hnew[1]);
            float r0 = hnew[0] - __bfloat162float(__low2bfloat16(h2));
            float r1 = hnew[1] - __bfloat162float(__high2bfloat16(h2));
            __nv_bfloat162 l2v = __floats2bfloat162_rn(r0, r1);

            *(__nv_bfloat162*)(g_hhi + i) = h2;
            *(__nv_bfloat162*)(g_hlo + i) = l2v;

            size_t oidx = ((size_t)t * BB + b) * INK + (size_t)d2 * HH + jp;
            *(__nv_bfloat162*)(g_ahi + oidx) = h2;
            *(__nv_bfloat162*)(g_alo + oidx) = l2v;

            if (s == TT - 1) *(float2*)(hn_out + i) = make_float2(hnew[0], hnew[1]);
        }

        grid_sync(phase);
    }
}

// ---------------------------------------------------------------------------
// Launch
// ---------------------------------------------------------------------------
extern "C" void kernel_launch(void* const* d_in, const int* in_sizes, int n_in,
                              void* d_out, int out_size) {
    const float* x   = (const float*)d_in[0];  // [T, B, 2048]
    const float* h0  = (const float*)d_in[1];  // [6, B, H]
    const float* wih = (const float*)d_in[2];  // [3, 2, 3072, 2048]
    const float* whh = (const float*)d_in[3];  // [3, 2, 3072, 1024]
    const float* bih = (const float*)d_in[4];  // [3, 2, 3072]
    const float* bhh = (const float*)d_in[5];  // [3, 2, 3072]
    float* out = (float*)d_out;                // [6, B, H]

    __nv_bfloat16 *ahi, *alo, *whi, *wlo, *uhi, *ulo;
    cudaGetSymbolAddress((void**)&ahi, g_ahi);
    cudaGetSymbolAddress((void**)&alo, g_alo);
    cudaGetSymbolAddress((void**)&whi, g_whi);
    cudaGetSymbolAddress((void**)&wlo, g_wlo);
    cudaGetSymbolAddress((void**)&uhi, g_uhi);
    cudaGetSymbolAddress((void**)&ulo, g_ulo);

    cudaFuncSetAttribute(gx_mma_kernel,
                         cudaFuncAttributeMaxDynamicSharedMemorySize, GX_SMEM);
    cudaFuncSetAttribute(gru_recurrent_kernel,
                         cudaFuncAttributeMaxDynamicSharedMemorySize, RC_SMEM);

    {   // split w_ih
        size_t n4 = (size_t)6 * IN3H * INK / 4;
        split_bf16_kernel<<<(unsigned)((n4 + 255) / 256), 256>>>(wih, whi, wlo, n4);
    }
    {   // split w_hh
        size_t n4 = (size_t)6 * IN3H * HH / 4;
        split_bf16_kernel<<<(unsigned)((n4 + 255) / 256), 256>>>(whh, uhi, ulo, n4);
    }
    {   // split x (layer-0 input)
        size_t n4 = (size_t)GX_M * INK / 4;
        split_bf16_kernel<<<(unsigned)((n4 + 255) / 256), 256>>>(x, ahi, alo, n4);
    }

    for (int l = 0; l < 3; l++) {
        gx_mma_kernel<<<dim3(IN3H / 128, GX_M / 128, 2), 256, GX_SMEM>>>(
            whi + (size_t)l * 2 * IN3H * INK,
            wlo + (size_t)l * 2 * IN3H * INK,
            bih + (size_t)l * 2 * IN3H);

        gru_recurrent_kernel<<<REC_BLOCKS, REC_THREADS, RC_SMEM>>>(
            h0  + (size_t)l * 2 * BB * HH,
            uhi + (size_t)l * 2 * IN3H * HH,
            ulo + (size_t)l * 2 * IN3H * HH,
            bhh + (size_t)l * 2 * IN3H,
            out + (size_t)l * 2 * BB * HH);
    }
}